// round 2
// baseline (speedup 1.0000x reference)
#include <cuda_runtime.h>
#include <cstdint>

#define N_PULSES 64
#define N_STATES 21
#define THREADS  256
#define WARPS_PER_BLOCK (THREADS / 32)

// Read TR robustly on-device: int 500 reads as a small positive int; a float
// 500.0f bit-pattern (0x43FA0000) reads as a huge int -> reinterpret as float.
__device__ __forceinline__ float read_scalar(const void* p)
{
    int iv = *(const int*)p;
    if (iv > 0 && iv < 1000000) return (float)iv;
    return *(const float*)p;
}

__global__ __launch_bounds__(THREADS)
void epg_kernel(const float* __restrict__ flip,
                const float* __restrict__ phases,
                const float* __restrict__ T1,
                const float* __restrict__ T2,
                const float* __restrict__ B0,
                const float* __restrict__ B1,
                const void*  __restrict__ TRp,
                float* __restrict__ out,
                int nbatch)
{
    __shared__ float4 s_trig[N_PULSES];  // (cos b, sin b, cos 2b, sin 2b)
    __shared__ float  s_a[N_PULSES];     // flip angle

    const int tid = threadIdx.x;
    if (tid < N_PULSES) {
        float b = phases[tid];
        float sb, cb;
        sincosf(b, &sb, &cb);            // precise version (once per block)
        s_trig[tid] = make_float4(cb, sb, cb * cb - sb * sb, 2.0f * cb * sb);
        s_a[tid] = flip[tid];
    }
    __syncthreads();

    const int lane = tid & 31;
    const int batch = blockIdx.x * WARPS_PER_BLOCK + (tid >> 5);
    if (batch >= nbatch) return;

    const float TR = read_scalar(TRp);

    // Per-batch constants (same value across all lanes of the warp)
    const float t1 = T1[batch];
    const float t2 = T2[batch];
    const float b0 = B0[batch];
    const float b1h = 0.5f * B1[batch];

    const float E1 = expf(-TR / t1);
    const float E2 = expf(-TR / t2);
    const float phi = 2.0f * 3.14159265358979f * b0 * TR * 0.001f;
    float sphi, cphi;
    sincosf(phi, &sphi, &cphi);          // precise: phi can be ~500 rad
    // Combined relax+precess complex multipliers: Fp *= E2*e^{+i phi}, Fm *= E2*e^{-i phi}
    const float cpr = E2 * cphi;
    const float cpi = E2 * sphi;
    const float zadd = (lane == 0) ? (1.0f - E1) : 0.0f;

    // State (lane = EPG order; lanes >= 21 stay exactly zero)
    float Fpr = 0.0f, Fpi = 0.0f, Fmr = 0.0f, Fmi = 0.0f;
    float Z = (lane == 0) ? 1.0f : 0.0f;

    const size_t cstride = (size_t)nbatch * N_STATES;       // component stride
    float* outp = out + (size_t)batch * N_STATES + lane;    // [t][c][batch][lane]
    const bool active = (lane < N_STATES);

#pragma unroll 2
    for (int t = 0; t < N_PULSES; ++t) {
        const float4 trig = s_trig[t];
        const float a = s_a[t];

        // Relaxation + B0 precession (fused complex scale)
        const float zr  = E1 * Z + zadd;
        const float npr = cpr * Fpr - cpi * Fpi;
        const float npi = cpr * Fpi + cpi * Fpr;
        const float nmr = cpr * Fmr + cpi * Fmi;
        const float nmi = cpr * Fmi - cpi * Fmr;

        // RF rotation coefficients
        const float ah = a * b1h;
        float sa, ca;
        __sincosf(ah, &sa, &ca);                   // arg in [0, ~1.9] — fast path safe
        const float ca2 = ca * ca;
        const float sa2 = sa * sa;
        const float casa = ca * sa;
        const float k1 = sa2 * trig.z;             // sa^2 * cos 2b
        const float k2 = sa2 * trig.w;             // sa^2 * sin 2b
        const float k3 = casa * trig.y;            // ca*sa * sin b
        const float k4 = casa * trig.x;            // ca*sa * cos b
        const float k7 = ca2 - sa2;

        const float Fpn_r =  ca2 * npr + k1 * nmr + k2 * nmi - k3 * zr;
        const float Fpn_i =  ca2 * npi + k2 * nmr - k1 * nmi + k4 * zr;
        const float Fmn_r =  k1 * npr - k2 * npi + ca2 * nmr - k3 * zr;
        const float Fmn_i = -k2 * npr - k1 * npi + ca2 * nmi - k4 * zr;
        const float Zn    =  k4 * (npi - nmi) - k3 * (npr + nmr) + k7 * zr;

        // Gradient shifts: Fp up one state, Fm down one state
        float sFpr = __shfl_up_sync(0xffffffffu, Fpn_r, 1);
        float sFpi = __shfl_up_sync(0xffffffffu, Fpn_i, 1);
        float sFmr = __shfl_down_sync(0xffffffffu, Fmn_r, 1);
        float sFmi = __shfl_down_sync(0xffffffffu, Fmn_i, 1);
        if (lane == 0 || lane >= N_STATES) { sFpr = 0.0f; sFpi = 0.0f; }
        if (lane >= N_STATES - 1)          { sFmr = 0.0f; sFmi = 0.0f; }
        Fpr = sFpr; Fpi = sFpi; Fmr = sFmr; Fmi = sFmi; Z = Zn;

        if (active) {
            float* o = outp + (size_t)t * 5u * cstride;
            o[0]           = Fpr;
            o[cstride]     = Fpi;
            o[2 * cstride] = Fmr;
            o[3 * cstride] = Fmi;
            o[4 * cstride] = Zn;
        }
    }
}

extern "C" void kernel_launch(void* const* d_in, const int* in_sizes, int n_in,
                              void* d_out, int out_size)
{
    const float* flip   = (const float*)d_in[0];
    const float* phases = (const float*)d_in[1];
    const float* T1     = (const float*)d_in[2];
    const float* T2     = (const float*)d_in[3];
    const float* B0     = (const float*)d_in[4];
    const float* B1     = (const float*)d_in[5];
    const void*  TRp    = d_in[6];

    const int nbatch = in_sizes[2];      // T1 element count = batch size
    float* out = (float*)d_out;
    const int blocks = (nbatch + WARPS_PER_BLOCK - 1) / WARPS_PER_BLOCK;
    epg_kernel<<<blocks, THREADS>>>(flip, phases, T1, T2, B0, B1, TRp, out, nbatch);
}

// round 3
// speedup vs baseline: 1.0959x; 1.0959x over previous
#include <cuda_runtime.h>
#include <cstdint>

#define N_PULSES 64
#define N_STATES 21
#define THREADS  256
#define WARPS_PER_BLOCK (THREADS / 32)

typedef unsigned long long u64;

// ---- packed f32x2 helpers (sm_100+ packed float ALU; FFMA2 in SASS) ----
__device__ __forceinline__ u64 pk(float lo, float hi) {
    u64 r; asm("mov.b64 %0,{%1,%2};" : "=l"(r) : "f"(lo), "f"(hi)); return r;
}
__device__ __forceinline__ void upk(u64 v, float& lo, float& hi) {
    asm("mov.b64 {%0,%1},%2;" : "=f"(lo), "=f"(hi) : "l"(v));
}
__device__ __forceinline__ u64 fma2(u64 a, u64 b, u64 c) {
    u64 d; asm("fma.rn.f32x2 %0,%1,%2,%3;" : "=l"(d) : "l"(a), "l"(b), "l"(c)); return d;
}
__device__ __forceinline__ u64 mul2(u64 a, u64 b) {
    u64 d; asm("mul.rn.f32x2 %0,%1,%2;" : "=l"(d) : "l"(a), "l"(b)); return d;
}

// TR scalar: int 500 reads small; float 500.0f bit pattern reads huge -> float path.
__device__ __forceinline__ float read_scalar(const void* p)
{
    int iv = *(const int*)p;
    if (iv > 0 && iv < 1000000) return (float)iv;
    return *(const float*)p;
}

__global__ __launch_bounds__(THREADS)
void epg_kernel(const float* __restrict__ flip,
                const float* __restrict__ phases,
                const float* __restrict__ T1,
                const float* __restrict__ T2,
                const float* __restrict__ B0,
                const float* __restrict__ B1,
                const void*  __restrict__ TRp,
                float* __restrict__ out,
                int nbatch)
{
    // Broadcast-packed trig table: per pulse 8 u64 pairs
    // [0]=cb, [1]=c2b, [2]=s2b, [3]=-sb, [4]=-cb, [5]=-c2b, [6]=-s2b, [7]=flip (as pair)
    __shared__ u64 s_tp[N_PULSES][8];

    const int tid = threadIdx.x;
    if (tid < N_PULSES) {
        float b = phases[tid];
        float sb, cb;
        sincosf(b, &sb, &cb);                 // precise, once per block
        float c2b = cb * cb - sb * sb;
        float s2b = 2.0f * cb * sb;
        s_tp[tid][0] = pk(cb, cb);
        s_tp[tid][1] = pk(c2b, c2b);
        s_tp[tid][2] = pk(s2b, s2b);
        s_tp[tid][3] = pk(-sb, -sb);
        s_tp[tid][4] = pk(-cb, -cb);
        s_tp[tid][5] = pk(-c2b, -c2b);
        s_tp[tid][6] = pk(-s2b, -s2b);
        float a = flip[tid];
        s_tp[tid][7] = pk(a, a);
    }
    __syncthreads();

    const int lane = tid & 31;
    const int warp = tid >> 5;
    const int b0 = (blockIdx.x * WARPS_PER_BLOCK + warp) * 2;
    if (b0 >= nbatch) return;
    const int  b1    = (b0 + 1 < nbatch) ? b0 + 1 : b0;
    const bool hi_ok = (b0 + 1 < nbatch);

    const float TR = read_scalar(TRp);

    // Per-batch-pair constants
    const float E1a = expf(-TR / T1[b0]), E1b = expf(-TR / T1[b1]);
    const float E2a = expf(-TR / T2[b0]), E2b = expf(-TR / T2[b1]);
    float spa, cpa, spb, cpb;
    {
        const float TWO_PI_ML = 2.0f * 3.14159265358979f * 0.001f;
        sincosf(TWO_PI_ML * B0[b0] * TR, &spa, &cpa);   // precise (large arg)
        sincosf(TWO_PI_ML * B0[b1] * TR, &spb, &cpb);
    }
    const u64 E1p   = pk(E1a, E1b);
    const u64 cprp  = pk(E2a * cpa,  E2b * cpb);   // Re(E2 e^{+i phi})
    const u64 cpip  = pk(E2a * spa,  E2b * spb);   // Im
    const u64 cpinp = pk(-E2a * spa, -E2b * spb);  // -Im
    const u64 zaddp = (lane == 0) ? pk(1.0f - E1a, 1.0f - E1b) : 0ull;
    const float b1ha = 0.5f * B1[b0], b1hb = 0.5f * B1[b1];
    const u64 m2p  = pk(-2.0f, -2.0f);
    const u64 onep = pk(1.0f, 1.0f);

    // Packed state (lane = EPG order; lanes >= 21 stay zero)
    u64 Fpr = 0ull, Fpi = 0ull, Fmr = 0ull, Fmi = 0ull;
    u64 Zp = (lane == 0) ? pk(1.0f, 1.0f) : 0ull;

    const size_t cs = (size_t)nbatch * N_STATES;           // component stride
    float* o = out + (size_t)b0 * N_STATES + lane;         // [t][c][batch][state]
    const bool active = (lane < N_STATES);

#pragma unroll 2
    for (int t = 0; t < N_PULSES; ++t) {
        const u64* tp = s_tp[t];

        // Relaxation + B0 precession (packed complex scale)
        const u64 zr  = fma2(E1p, Zp, zaddp);
        const u64 npr = fma2(cprp, Fpr, mul2(cpinp, Fpi));
        const u64 npi = fma2(cprp, Fpi, mul2(cpip,  Fpr));
        const u64 nmr = fma2(cprp, Fmr, mul2(cpip,  Fmi));
        const u64 nmi = fma2(cprp, Fmi, mul2(cpinp, Fmr));

        // RF rotation coefficients (packed)
        float aa, ab_;
        upk(tp[7], aa, ab_);
        float sa0, ca0, sa1, ca1;
        __sincosf(aa * b1ha, &sa0, &ca0);      // arg in [0,~1.9] fast-path safe
        __sincosf(ab_ * b1hb, &sa1, &ca1);
        const u64 sap   = pk(sa0, sa1);
        const u64 cap   = pk(ca0, ca1);
        const u64 ca2p  = mul2(cap, cap);
        const u64 sa2p  = mul2(sap, sap);
        const u64 casap = mul2(cap, sap);
        const u64 k1  = mul2(sa2p, tp[1]);     // sa^2 *  cos2b
        const u64 k2  = mul2(sa2p, tp[2]);     // sa^2 *  sin2b
        const u64 k1n = mul2(sa2p, tp[5]);     // sa^2 * -cos2b
        const u64 k2n = mul2(sa2p, tp[6]);     // sa^2 * -sin2b
        const u64 k3n = mul2(casap, tp[3]);    // casa * -sinb
        const u64 k4  = mul2(casap, tp[0]);    // casa *  cosb
        const u64 k4n = mul2(casap, tp[4]);    // casa * -cosb
        const u64 k7  = fma2(sa2p, m2p, onep); // 1 - 2 sa^2 = ca^2 - sa^2

        const u64 Fpn_r = fma2(k3n, zr, fma2(k2,  nmi, fma2(k1,  nmr, mul2(ca2p, npr))));
        const u64 Fpn_i = fma2(k4,  zr, fma2(k1n, nmi, fma2(k2,  nmr, mul2(ca2p, npi))));
        const u64 Fmn_r = fma2(k3n, zr, fma2(ca2p, nmr, fma2(k2n, npi, mul2(k1,  npr))));
        const u64 Fmn_i = fma2(k4n, zr, fma2(ca2p, nmi, fma2(k1n, npi, mul2(k2n, npr))));
        const u64 Zn    = fma2(k7,  zr, fma2(k3n, nmr, fma2(k3n, npr,
                                         fma2(k4n, nmi, mul2(k4, npi)))));

        // Gradient shifts: Fp up one state, Fm down one state (2 SHFL.32 each)
        u64 sFpr = __shfl_up_sync(0xffffffffu, Fpn_r, 1);
        u64 sFpi = __shfl_up_sync(0xffffffffu, Fpn_i, 1);
        u64 sFmr = __shfl_down_sync(0xffffffffu, Fmn_r, 1);
        u64 sFmi = __shfl_down_sync(0xffffffffu, Fmn_i, 1);
        if (lane == 0 || lane >= N_STATES) { sFpr = 0ull; sFpi = 0ull; }
        if (lane >= N_STATES - 1)          { sFmr = 0ull; sFmi = 0ull; }
        Fpr = sFpr; Fpi = sFpi; Fmr = sFmr; Fmi = sFmi; Zp = Zn;

        if (active) {
            float l0, h0, l1, h1, l2, h2, l3, h3, l4, h4;
            upk(Fpr, l0, h0); upk(Fpi, l1, h1);
            upk(Fmr, l2, h2); upk(Fmi, l3, h3); upk(Zn, l4, h4);
            float* ot = o + (size_t)t * 5u * cs;
            ot[0]      = l0;
            ot[cs]     = l1;
            ot[2 * cs] = l2;
            ot[3 * cs] = l3;
            ot[4 * cs] = l4;
            if (hi_ok) {
                ot[N_STATES]          = h0;
                ot[N_STATES + cs]     = h1;
                ot[N_STATES + 2 * cs] = h2;
                ot[N_STATES + 3 * cs] = h3;
                ot[N_STATES + 4 * cs] = h4;
            }
        }
    }
}

extern "C" void kernel_launch(void* const* d_in, const int* in_sizes, int n_in,
                              void* d_out, int out_size)
{
    const float* flip   = (const float*)d_in[0];
    const float* phases = (const float*)d_in[1];
    const float* T1     = (const float*)d_in[2];
    const float* T2     = (const float*)d_in[3];
    const float* B0     = (const float*)d_in[4];
    const float* B1     = (const float*)d_in[5];
    const void*  TRp    = d_in[6];

    const int nbatch = in_sizes[2];          // T1 element count = batch
    float* out = (float*)d_out;
    const int nwarps = (nbatch + 1) / 2;     // 2 batches per warp
    const int blocks = (nwarps + WARPS_PER_BLOCK - 1) / WARPS_PER_BLOCK;
    epg_kernel<<<blocks, THREADS>>>(flip, phases, T1, T2, B0, B1, TRp, out, nbatch);
}

// round 4
// speedup vs baseline: 1.2835x; 1.1712x over previous
#include <cuda_runtime.h>
#include <cstdint>

#define N_PULSES 64
#define N_STATES 21
#define THREADS  256
#define WARPS_PER_BLOCK (THREADS / 32)

typedef unsigned long long u64;

// ---- packed f32x2 helpers (FFMA2 in SASS; reachable only via PTX f32x2) ----
__device__ __forceinline__ u64 pk(float lo, float hi) {
    u64 r; asm("mov.b64 %0,{%1,%2};" : "=l"(r) : "f"(lo), "f"(hi)); return r;
}
__device__ __forceinline__ void upk(u64 v, float& lo, float& hi) {
    asm("mov.b64 {%0,%1},%2;" : "=f"(lo), "=f"(hi) : "l"(v));
}
__device__ __forceinline__ u64 fma2(u64 a, u64 b, u64 c) {
    u64 d; asm("fma.rn.f32x2 %0,%1,%2,%3;" : "=l"(d) : "l"(a), "l"(b), "l"(c)); return d;
}
__device__ __forceinline__ u64 mul2(u64 a, u64 b) {
    u64 d; asm("mul.rn.f32x2 %0,%1,%2;" : "=l"(d) : "l"(a), "l"(b)); return d;
}

// TR scalar: int 500 reads small; float 500.0f bit pattern reads huge -> float.
__device__ __forceinline__ float read_scalar(const void* p)
{
    int iv = *(const int*)p;
    if (iv > 0 && iv < 1000000) return (float)iv;
    return *(const float*)p;
}

__global__ __launch_bounds__(THREADS, 1)
void epg_kernel(const float* __restrict__ flip,
                const float* __restrict__ phases,
                const float* __restrict__ T1,
                const float* __restrict__ T2,
                const float* __restrict__ B0,
                const float* __restrict__ B1,
                const void*  __restrict__ TRp,
                float* __restrict__ out,
                int nbatch)
{
    // Broadcast-packed trig table (batch-independent, shared by both chains):
    // [0]=cb, [1]=c2b, [2]=s2b, [3]=-sb, [4]=-cb, [5]=-c2b, [6]=-s2b, [7]=flip
    __shared__ u64 s_tp[N_PULSES][8];

    const int tid = threadIdx.x;
    if (tid < N_PULSES) {
        float b = phases[tid];
        float sb, cb;
        sincosf(b, &sb, &cb);                 // precise, once per block
        float c2b = cb * cb - sb * sb;
        float s2b = 2.0f * cb * sb;
        s_tp[tid][0] = pk(cb, cb);
        s_tp[tid][1] = pk(c2b, c2b);
        s_tp[tid][2] = pk(s2b, s2b);
        s_tp[tid][3] = pk(-sb, -sb);
        s_tp[tid][4] = pk(-cb, -cb);
        s_tp[tid][5] = pk(-c2b, -c2b);
        s_tp[tid][6] = pk(-s2b, -s2b);
        float a = flip[tid];
        s_tp[tid][7] = pk(a, a);
    }
    __syncthreads();

    const int lane = tid & 31;
    const int warp = tid >> 5;
    const int base = (blockIdx.x * WARPS_PER_BLOCK + warp) * 4;
    if (base >= nbatch) return;

    // Chain A: batches base, base+1.  Chain B: batches base+2, base+3.
    const int  iA0 = base;
    const int  iA1 = (base + 1 < nbatch) ? base + 1 : base;
    const bool hiA = (base + 1 < nbatch);
    const bool okB = (base + 2 < nbatch);
    const int  iB0 = okB ? base + 2 : base;
    const int  iB1 = (base + 3 < nbatch) ? base + 3 : iB0;
    const bool hiB = (base + 3 < nbatch);

    const float TR = read_scalar(TRp);
    const float TWO_PI_ML = 2.0f * 3.14159265358979f * 0.001f;

#define MK_CONST(S, i0, i1)                                                    \
    const float E1a##S = expf(-TR / T1[i0]), E1b##S = expf(-TR / T1[i1]);      \
    const float E2a##S = expf(-TR / T2[i0]), E2b##S = expf(-TR / T2[i1]);      \
    float spa##S, cpa##S, spb##S, cpb##S;                                      \
    sincosf(TWO_PI_ML * B0[i0] * TR, &spa##S, &cpa##S);                        \
    sincosf(TWO_PI_ML * B0[i1] * TR, &spb##S, &cpb##S);                        \
    const u64 E1p##S  = pk(E1a##S, E1b##S);                                    \
    const u64 cpr##S  = pk(E2a##S * cpa##S,  E2b##S * cpb##S);                 \
    const u64 cpi##S  = pk(E2a##S * spa##S,  E2b##S * spb##S);                 \
    const u64 cpin##S = pk(-E2a##S * spa##S, -E2b##S * spb##S);                \
    const u64 zadd##S = (lane == 0) ? pk(1.0f - E1a##S, 1.0f - E1b##S) : 0ull; \
    const float b1h0##S = 0.5f * B1[i0], b1h1##S = 0.5f * B1[i1];

    MK_CONST(A, iA0, iA1)
    MK_CONST(B, iB0, iB1)
#undef MK_CONST

    const u64 m2p  = pk(-2.0f, -2.0f);
    const u64 onep = pk(1.0f, 1.0f);

    // Packed state (lane = EPG order; lanes >= 21 stay exactly zero)
    u64 FprA = 0ull, FpiA = 0ull, FmrA = 0ull, FmiA = 0ull;
    u64 FprB = 0ull, FpiB = 0ull, FmrB = 0ull, FmiB = 0ull;
    u64 ZA = (lane == 0) ? pk(1.0f, 1.0f) : 0ull;
    u64 ZB = ZA;

    const size_t cs = (size_t)nbatch * N_STATES;            // component stride
    float* oA = out + (size_t)iA0 * N_STATES + lane;        // [t][c][batch][state]
    const bool active = (lane < N_STATES);
    const bool edgeFp = (lane == 0 || lane >= N_STATES);
    const bool edgeFm = (lane >= N_STATES - 1);

    // One full state advance for one packed chain: relax+precess, RF rotation,
    // writes new (pre-shift) values into Fpn_/Fmn_/Zn_ outputs.
#define ADVANCE(S, Fpn, Fpi_n, Fmn, Fmi_n, Zn)                                 \
    u64 Fpn, Fpi_n, Fmn, Fmi_n, Zn;                                            \
    {                                                                          \
        const u64 zr  = fma2(E1p##S, Z##S, zadd##S);                           \
        const u64 npr = fma2(cpr##S, Fpr##S, mul2(cpin##S, Fpi##S));           \
        const u64 npi = fma2(cpr##S, Fpi##S, mul2(cpi##S,  Fpr##S));           \
        const u64 nmr = fma2(cpr##S, Fmr##S, mul2(cpi##S,  Fmi##S));           \
        const u64 nmi = fma2(cpr##S, Fmi##S, mul2(cpin##S, Fmr##S));           \
        float sa0, ca0, sa1, ca1;                                              \
        __sincosf(aflip * b1h0##S, &sa0, &ca0);                                \
        __sincosf(aflip * b1h1##S, &sa1, &ca1);                                \
        const u64 sap   = pk(sa0, sa1);                                        \
        const u64 cap   = pk(ca0, ca1);                                        \
        const u64 ca2p  = mul2(cap, cap);                                      \
        const u64 sa2p  = mul2(sap, sap);                                      \
        const u64 casap = mul2(cap, sap);                                      \
        const u64 k1  = mul2(sa2p, tp1);                                       \
        const u64 k2  = mul2(sa2p, tp2);                                       \
        const u64 k1n = mul2(sa2p, tp5);                                       \
        const u64 k2n = mul2(sa2p, tp6);                                       \
        const u64 k3n = mul2(casap, tp3);                                      \
        const u64 k4  = mul2(casap, tp0);                                      \
        const u64 k4n = mul2(casap, tp4);                                      \
        const u64 k7  = fma2(sa2p, m2p, onep);                                 \
        Fpn   = fma2(k3n, zr, fma2(k2,  nmi, fma2(k1,  nmr, mul2(ca2p, npr))));\
        Fpi_n = fma2(k4,  zr, fma2(k1n, nmi, fma2(k2,  nmr, mul2(ca2p, npi))));\
        Fmn   = fma2(k3n, zr, fma2(ca2p, nmr, fma2(k2n, npi, mul2(k1, npr)))); \
        Fmi_n = fma2(k4n, zr, fma2(ca2p, nmi, fma2(k1n, npi, mul2(k2n, npr))));\
        Zn    = fma2(k7,  zr, fma2(k3n, nmr, fma2(k3n, npr,                    \
                                  fma2(k4n, nmi, mul2(k4, npi)))));            \
    }

#define STORE5(ptr, v0, v1, v2, v3, v4, off, half)                             \
    {                                                                          \
        float l0,h0,l1,h1,l2,h2,l3,h3,l4,h4;                                   \
        upk(v0,l0,h0); upk(v1,l1,h1); upk(v2,l2,h2);                           \
        upk(v3,l3,h3); upk(v4,l4,h4);                                          \
        (ptr)[(off)]          = l0;                                            \
        (ptr)[(off) + cs]     = l1;                                            \
        (ptr)[(off) + 2*cs]   = l2;                                            \
        (ptr)[(off) + 3*cs]   = l3;                                            \
        (ptr)[(off) + 4*cs]   = l4;                                            \
        if (half) {                                                            \
            (ptr)[(off) + N_STATES]        = h0;                               \
            (ptr)[(off) + N_STATES + cs]   = h1;                               \
            (ptr)[(off) + N_STATES + 2*cs] = h2;                               \
            (ptr)[(off) + N_STATES + 3*cs] = h3;                               \
            (ptr)[(off) + N_STATES + 4*cs] = h4;                               \
        }                                                                      \
    }

#pragma unroll 1
    for (int t = 0; t < N_PULSES; ++t) {
        const u64* tp = s_tp[t];
        const u64 tp0 = tp[0], tp1 = tp[1], tp2 = tp[2], tp3 = tp[3];
        const u64 tp4 = tp[4], tp5 = tp[5], tp6 = tp[6];
        float aflip, dummy;
        upk(tp[7], aflip, dummy);

        // --- chain A compute, then launch its shuffles ---
        ADVANCE(A, FpnA, FpinA, FmnA, FminA, ZnA)
        u64 sFprA = __shfl_up_sync(0xffffffffu, FpnA, 1);
        u64 sFpiA = __shfl_up_sync(0xffffffffu, FpinA, 1);
        u64 sFmrA = __shfl_down_sync(0xffffffffu, FmnA, 1);
        u64 sFmiA = __shfl_down_sync(0xffffffffu, FminA, 1);

        // --- chain B compute fills chain A's shuffle latency ---
        ADVANCE(B, FpnB, FpinB, FmnB, FminB, ZnB)
        u64 sFprB = __shfl_up_sync(0xffffffffu, FpnB, 1);
        u64 sFpiB = __shfl_up_sync(0xffffffffu, FpinB, 1);
        u64 sFmrB = __shfl_down_sync(0xffffffffu, FmnB, 1);
        u64 sFmiB = __shfl_down_sync(0xffffffffu, FminB, 1);

        if (edgeFp) { sFprA = 0ull; sFpiA = 0ull; sFprB = 0ull; sFpiB = 0ull; }
        if (edgeFm) { sFmrA = 0ull; sFmiA = 0ull; sFmrB = 0ull; sFmiB = 0ull; }
        FprA = sFprA; FpiA = sFpiA; FmrA = sFmrA; FmiA = sFmiA; ZA = ZnA;
        FprB = sFprB; FpiB = sFpiB; FmrB = sFmrB; FmiB = sFmiB; ZB = ZnB;

        if (active) {
            float* ot = oA + (size_t)t * 5u * cs;
            STORE5(ot, FprA, FpiA, FmrA, FmiA, ZnA, 0, hiA)
            if (okB)
                STORE5(ot, FprB, FpiB, FmrB, FmiB, ZnB, 2 * N_STATES, hiB)
        }
    }
#undef ADVANCE
#undef STORE5
}

extern "C" void kernel_launch(void* const* d_in, const int* in_sizes, int n_in,
                              void* d_out, int out_size)
{
    const float* flip   = (const float*)d_in[0];
    const float* phases = (const float*)d_in[1];
    const float* T1     = (const float*)d_in[2];
    const float* T2     = (const float*)d_in[3];
    const float* B0     = (const float*)d_in[4];
    const float* B1     = (const float*)d_in[5];
    const void*  TRp    = d_in[6];

    const int nbatch = in_sizes[2];          // T1 element count = batch
    float* out = (float*)d_out;
    const int nwarps = (nbatch + 3) / 4;     // 4 batches per warp (2 chains)
    const int blocks = (nwarps + WARPS_PER_BLOCK - 1) / WARPS_PER_BLOCK;
    epg_kernel<<<blocks, THREADS>>>(flip, phases, T1, T2, B0, B1, TRp, out, nbatch);
}